// round 15
// baseline (speedup 1.0000x reference)
#include <cuda_runtime.h>

// Problem constants
#define HH   112
#define WW   112
#define CROP 28
#define CW   56
#define NPIX (CW * CW)
#define BB   128
#define MM   64
#define TT   12
#define HID  64
#define OUTD 36

#define NTHR 128
#define AUX_BLOCKS BB            // 1 block per batch
#define MOT_BLOCKS 4
#define NBLK (AUX_BLOCKS + MOT_BLOCKS)   // 132 <= 148 : one wave

__device__ float g_aux_partial[AUX_BLOCKS];
__device__ float g_mot_partial[MOT_BLOCKS];
__device__ int   g_count = 0;

#define FMA2(acc, x, y) \
    asm("fma.rn.f32x2 %0, %1, %2, %0;" : "+l"(acc) : "l"(x), "l"(y))

__global__ __launch_bounds__(NTHR) void fused_kernel(
    const int*   __restrict__ goal_pixel,   // [B,2] (col,row)
    const int*   __restrict__ obj_list,     // [B,M,2] (col,row)
    const int*   __restrict__ obj_num,      // [B]
    const int*   __restrict__ road_mask,    // [B,112,112]
    const float* __restrict__ logits,       // [B,56,56]
    const float* __restrict__ tpos,         // [B,T,2]
    const float* __restrict__ tyaw,         // [B,T]
    const float* __restrict__ w1, const float* __restrict__ b1,
    const float* __restrict__ w2, const float* __restrict__ b2,
    float*       __restrict__ out)
{
    const int blk = blockIdx.x;
    const int tid = threadIdx.x;

    // smem: rowfd first for 16B alignment
    __shared__ __align__(16) unsigned long long rowfd[MM * CW]; // 28KB [m][r] dup'd
    __shared__ __align__(16) float colf[MM * 64];               // 16KB [m][c]
    __shared__ float tabc[384];      // exp(-(i-112)^2/8); zero for far indices
    __shared__ int   s_ox[MM], s_oy[MM];
    __shared__ float s_warp[4];
    __shared__ bool  s_last;

    if (blk < AUX_BLOCKS) {
        // ======== aux: one full 56x56 crop of one batch ========
        const int b  = blk;
        const int rt = tid >> 4;          // row tile 0..7 (7 valid)
        const int ct = tid & 15;          // col tile 0..15 (14 valid)
        const int rteff = (rt < 7) ? rt : 6;

        for (int i = tid; i < 384; i += NTHR) {
            float d = (float)(i - 112);
            tabc[i] = __expf(-d * d * 0.125f);
        }
        if (tid < MM) {
            int nobj = obj_num[b];
            nobj = nobj < 0 ? 0 : (nobj > MM ? MM : nobj);
            int2 o = ((const int2*)obj_list)[b * MM + tid];
            if (tid >= nobj) { o.x = -160; o.y = -160; }  // -> zero zone
            s_ox[tid] = o.x;   // col
            s_oy[tid] = o.y;   // row
        }
        const int yg = goal_pixel[2 * b + 0];
        const int xg = goal_pixel[2 * b + 1];
        __syncthreads();

        // colf[m][c] = tab(c+28 - ox[m]), c in [0,64)
        for (int i = tid; i < MM * 64; i += NTHR) {
            const int m = i >> 6, c = i & 63;
            colf[i] = tabc[c + CROP + 112 - s_ox[m]];
        }
        // rowfd[m][r] = dup(tab(r+28 - oy[m])), r in [0,56)
        for (int i = tid; i < MM * CW; i += NTHR) {
            const int m = i / CW, r = i - m * CW;
            const float v = tabc[r + CROP + 112 - s_oy[m]];
            unsigned long long d;
            asm("mov.b64 %0, {%1, %1};" : "=l"(d) : "f"(v));
            rowfd[i] = d;
        }
        __syncthreads();

        // ======== object loop: 16 f32x2 accumulators, rt-bound FFMA2 ========
        unsigned long long a[16];
        #pragma unroll
        for (int i = 0; i < 16; i++) a[i] = 0ull;

        const ulonglong2* pc = ((const ulonglong2*)colf) + ct;       // + m*16
        const ulonglong2* pr = ((const ulonglong2*)rowfd) + rteff * 4; // + m*28

        #pragma unroll
        for (int m = 0; m < MM; m++) {
            const ulonglong2 cf  = pc[m * 16];      // (c0,c1),(c2,c3)
            const ulonglong2 r01 = pr[m * 28 + 0];  // dup r0, dup r1
            const ulonglong2 r23 = pr[m * 28 + 1];
            const ulonglong2 r45 = pr[m * 28 + 2];
            const ulonglong2 r67 = pr[m * 28 + 3];
            FMA2(a[0],  cf.x, r01.x); FMA2(a[1],  cf.y, r01.x);
            FMA2(a[2],  cf.x, r01.y); FMA2(a[3],  cf.y, r01.y);
            FMA2(a[4],  cf.x, r23.x); FMA2(a[5],  cf.y, r23.x);
            FMA2(a[6],  cf.x, r23.y); FMA2(a[7],  cf.y, r23.y);
            FMA2(a[8],  cf.x, r45.x); FMA2(a[9],  cf.y, r45.x);
            FMA2(a[10], cf.x, r45.y); FMA2(a[11], cf.y, r45.y);
            FMA2(a[12], cf.x, r67.x); FMA2(a[13], cf.y, r67.x);
            FMA2(a[14], cf.x, r67.y); FMA2(a[15], cf.y, r67.y);
        }

        // ======== epilogue: softplus + BCE over this thread's 8x4 tile ========
        float local = 0.0f;
        if (rt < 7 && ct < 14) {
            const int r0 = rt * 8, c0 = ct * 4;
            const float4* lg = (const float4*)(logits + b * NPIX + r0 * CW + c0);
            const int4*   rm = (const int4*)(road_mask
                               + (b * HH + r0 + CROP) * WW + c0 + CROP);
            float gc[4];
            #pragma unroll
            for (int u = 0; u < 4; u++)
                gc[u] = tabc[c0 + u + CROP + 112 - yg];

            #pragma unroll
            for (int k = 0; k < 8; k++) {
                const float4 z4 = lg[k * (CW / 4)];
                const int4   m4 = rm[k * (WW / 4)];
                const float  gr = tabc[r0 + k + CROP + 112 - xg];
                float s[4];
                asm("mov.b64 {%0, %1}, %2;" : "=f"(s[0]), "=f"(s[1]) : "l"(a[2*k]));
                asm("mov.b64 {%0, %1}, %2;" : "=f"(s[2]), "=f"(s[3]) : "l"(a[2*k+1]));
                const float zz[4] = {z4.x, z4.y, z4.z, z4.w};
                const int   mm[4] = {m4.x, m4.y, m4.z, m4.w};
                #pragma unroll
                for (int u = 0; u < 4; u++) {
                    const float z  = zz[u];
                    const float sp = fmaxf(z, 0.0f)
                                   + __logf(1.0f + __expf(-fabsf(z)));
                    float gt = 0.0f;
                    if (mm[u] != 0)
                        gt = 0.5f + 0.5f * (gc[u] * gr) - 0.5f * s[u];
                    local += sp - z * gt;
                }
            }
        }

        #pragma unroll
        for (int off = 16; off > 0; off >>= 1)
            local += __shfl_down_sync(0xffffffffu, local, off);
        if ((tid & 31) == 0) s_warp[tid >> 5] = local;
        __syncthreads();
        if (tid == 0)
            g_aux_partial[blk] = s_warp[0] + s_warp[1] + s_warp[2] + s_warp[3];
    } else {
        // ======== motion MLP loss (512 lanes over 4 blocks) ========
        const int mt = (blk - AUX_BLOCKS) * NTHR + tid;   // 0..511
        float part = 0.0f;
        {
            const int b  = mt >> 2;
            const int og = mt & 3;

            const float x0 = (float)goal_pixel[2 * b + 0];
            const float x1 = (float)goal_pixel[2 * b + 1];

            float h[HID];
            #pragma unroll
            for (int j = 0; j < HID; j++) {
                float v = fmaf(x0, w1[j], fmaf(x1, w1[HID + j], b1[j]));
                h[j] = fmaxf(v, 0.0f);
            }
            float acc[9];
            #pragma unroll
            for (int u = 0; u < 9; u++) acc[u] = b2[og * 9 + u];
            for (int j = 0; j < HID; j++) {
                const float hv = h[j];
                const float* wr = w2 + j * OUTD + og * 9;
                #pragma unroll
                for (int u = 0; u < 9; u++)
                    acc[u] = fmaf(hv, wr[u], acc[u]);
            }
            #pragma unroll
            for (int u = 0; u < 9; u++) {
                const int o = og * 9 + u;
                const int t = o / 3, uu = o % 3;
                const float tgt = (uu < 2) ? tpos[(b * TT + t) * 2 + uu]
                                           : tyaw[b * TT + t];
                const float d = acc[u] - tgt;
                part = fmaf(d, d, part);
            }
        }
        #pragma unroll
        for (int off = 16; off > 0; off >>= 1)
            part += __shfl_down_sync(0xffffffffu, part, off);
        if ((tid & 31) == 0) s_warp[tid >> 5] = part;
        __syncthreads();
        if (tid == 0)
            g_mot_partial[blk - AUX_BLOCKS] =
                s_warp[0] + s_warp[1] + s_warp[2] + s_warp[3];
    }

    // ======== last-block-done final combine ========
    __syncthreads();
    __threadfence();
    if (tid == 0) {
        int old = atomicAdd(&g_count, 1);
        s_last = (old == NBLK - 1);
    }
    __syncthreads();

    if (s_last) {
        __threadfence();
        float v = g_aux_partial[tid];        // 128 partials, 1 per thread
        #pragma unroll
        for (int off = 16; off > 0; off >>= 1)
            v += __shfl_down_sync(0xffffffffu, v, off);
        if ((tid & 31) == 0) s_warp[tid >> 5] = v;
        __syncthreads();
        if (tid == 0) {
            const float aux = s_warp[0] + s_warp[1] + s_warp[2] + s_warp[3];
            const float mot = (g_mot_partial[0] + g_mot_partial[1]
                             + g_mot_partial[2] + g_mot_partial[3])
                              * (1.0f / (float)(BB * OUTD));
            out[0] = mot + aux;
            out[1] = aux;
            out[2] = mot;
            g_count = 0;   // reset for next graph replay
        }
    }
}

extern "C" void kernel_launch(void* const* d_in, const int* in_sizes, int n_in,
                              void* d_out, int out_size)
{
    const int*   goal_pixel = (const int*)  d_in[0];
    const int*   obj_list   = (const int*)  d_in[1];
    const int*   obj_num    = (const int*)  d_in[2];
    const int*   road_mask  = (const int*)  d_in[3];
    const float* logits     = (const float*)d_in[4];
    const float* tpos       = (const float*)d_in[5];
    const float* tyaw       = (const float*)d_in[6];
    const float* w1         = (const float*)d_in[7];
    const float* b1         = (const float*)d_in[8];
    const float* w2         = (const float*)d_in[9];
    const float* b2         = (const float*)d_in[10];
    float* out = (float*)d_out;

    fused_kernel<<<NBLK, NTHR>>>(goal_pixel, obj_list, obj_num, road_mask,
                                 logits, tpos, tyaw, w1, b1, w2, b2, out);
}

// round 16
// speedup vs baseline: 1.0025x; 1.0025x over previous
#include <cuda_runtime.h>

// Problem constants
#define HH   112
#define WW   112
#define CROP 28
#define CW   56
#define NPIX (CW * CW)
#define BB   128
#define MM   64
#define TT   12
#define HID  64
#define OUTD 36

#define NTHR 128
#define AUX_BLOCKS BB            // 1 block per batch
#define MOT_BLOCKS 4
#define NBLK (AUX_BLOCKS + MOT_BLOCKS)   // 132 <= 148 : one wave

__device__ float g_aux_partial[AUX_BLOCKS];
__device__ float g_mot_partial[MOT_BLOCKS];
__device__ int   g_count = 0;

#define FMA2(acc, x, y) \
    asm("fma.rn.f32x2 %0, %1, %2, %0;" : "+l"(acc) : "l"(x), "l"(y))

__global__ __launch_bounds__(NTHR) void fused_kernel(
    const int*   __restrict__ goal_pixel,   // [B,2] (col,row)
    const int*   __restrict__ obj_list,     // [B,M,2] (col,row)
    const int*   __restrict__ obj_num,      // [B]
    const int*   __restrict__ road_mask,    // [B,112,112]
    const float* __restrict__ logits,       // [B,56,56]
    const float* __restrict__ tpos,         // [B,T,2]
    const float* __restrict__ tyaw,         // [B,T]
    const float* __restrict__ w1, const float* __restrict__ b1,
    const float* __restrict__ w2, const float* __restrict__ b2,
    float*       __restrict__ out)
{
    const int blk = blockIdx.x;
    const int tid = threadIdx.x;

    // smem: rowfd first for 16B alignment
    __shared__ __align__(16) unsigned long long rowfd[MM * CW]; // 28KB [m][r] dup'd
    __shared__ __align__(16) float colf[MM * 64];               // 16KB [m][c]
    __shared__ float tabc[384];      // exp(-(i-112)^2/8); zero for far indices
    __shared__ int   s_ox[MM], s_oy[MM];
    __shared__ float s_warp[4];
    __shared__ bool  s_last;

    if (blk < AUX_BLOCKS) {
        // ======== aux: one full 56x56 crop of one batch ========
        const int b  = blk;
        const int rt = tid >> 4;          // row tile 0..7 (7 valid)
        const int ct = tid & 15;          // col tile 0..15 (14 valid)
        const int rteff = (rt < 7) ? rt : 6;

        for (int i = tid; i < 384; i += NTHR) {
            float d = (float)(i - 112);
            tabc[i] = __expf(-d * d * 0.125f);
        }
        if (tid < MM) {
            int nobj = obj_num[b];
            nobj = nobj < 0 ? 0 : (nobj > MM ? MM : nobj);
            int2 o = ((const int2*)obj_list)[b * MM + tid];
            if (tid >= nobj) { o.x = -160; o.y = -160; }  // -> zero zone
            s_ox[tid] = o.x;   // col
            s_oy[tid] = o.y;   // row
        }
        const int yg = goal_pixel[2 * b + 0];
        const int xg = goal_pixel[2 * b + 1];
        __syncthreads();

        // colf[m][c] = tab(c+28 - ox[m]), c in [0,64)
        for (int i = tid; i < MM * 64; i += NTHR) {
            const int m = i >> 6, c = i & 63;
            colf[i] = tabc[c + CROP + 112 - s_ox[m]];
        }
        // rowfd[m][r] = dup(tab(r+28 - oy[m])), r in [0,56)
        for (int i = tid; i < MM * CW; i += NTHR) {
            const int m = i / CW, r = i - m * CW;
            const float v = tabc[r + CROP + 112 - s_oy[m]];
            unsigned long long d;
            asm("mov.b64 %0, {%1, %1};" : "=l"(d) : "f"(v));
            rowfd[i] = d;
        }
        __syncthreads();

        // ======== object loop: 16 f32x2 accumulators, rt-bound FFMA2 ========
        unsigned long long a[16];
        #pragma unroll
        for (int i = 0; i < 16; i++) a[i] = 0ull;

        const ulonglong2* pc = ((const ulonglong2*)colf) + ct;       // + m*16
        const ulonglong2* pr = ((const ulonglong2*)rowfd) + rteff * 4; // + m*28

        #pragma unroll
        for (int m = 0; m < MM; m++) {
            const ulonglong2 cf  = pc[m * 16];      // (c0,c1),(c2,c3)
            const ulonglong2 r01 = pr[m * 28 + 0];  // dup r0, dup r1
            const ulonglong2 r23 = pr[m * 28 + 1];
            const ulonglong2 r45 = pr[m * 28 + 2];
            const ulonglong2 r67 = pr[m * 28 + 3];
            FMA2(a[0],  cf.x, r01.x); FMA2(a[1],  cf.y, r01.x);
            FMA2(a[2],  cf.x, r01.y); FMA2(a[3],  cf.y, r01.y);
            FMA2(a[4],  cf.x, r23.x); FMA2(a[5],  cf.y, r23.x);
            FMA2(a[6],  cf.x, r23.y); FMA2(a[7],  cf.y, r23.y);
            FMA2(a[8],  cf.x, r45.x); FMA2(a[9],  cf.y, r45.x);
            FMA2(a[10], cf.x, r45.y); FMA2(a[11], cf.y, r45.y);
            FMA2(a[12], cf.x, r67.x); FMA2(a[13], cf.y, r67.x);
            FMA2(a[14], cf.x, r67.y); FMA2(a[15], cf.y, r67.y);
        }

        // ======== epilogue: softplus + BCE over this thread's 8x4 tile ========
        float local = 0.0f;
        if (rt < 7 && ct < 14) {
            const int r0 = rt * 8, c0 = ct * 4;
            const float4* lg = (const float4*)(logits + b * NPIX + r0 * CW + c0);
            const int4*   rm = (const int4*)(road_mask
                               + (b * HH + r0 + CROP) * WW + c0 + CROP);
            float gc[4];
            #pragma unroll
            for (int u = 0; u < 4; u++)
                gc[u] = tabc[c0 + u + CROP + 112 - yg];

            #pragma unroll
            for (int k = 0; k < 8; k++) {
                const float4 z4 = lg[k * (CW / 4)];
                const int4   m4 = rm[k * (WW / 4)];
                const float  gr = tabc[r0 + k + CROP + 112 - xg];
                float s[4];
                asm("mov.b64 {%0, %1}, %2;" : "=f"(s[0]), "=f"(s[1]) : "l"(a[2*k]));
                asm("mov.b64 {%0, %1}, %2;" : "=f"(s[2]), "=f"(s[3]) : "l"(a[2*k+1]));
                const float zz[4] = {z4.x, z4.y, z4.z, z4.w};
                const int   mm[4] = {m4.x, m4.y, m4.z, m4.w};
                #pragma unroll
                for (int u = 0; u < 4; u++) {
                    const float z  = zz[u];
                    const float sp = fmaxf(z, 0.0f)
                                   + __logf(1.0f + __expf(-fabsf(z)));
                    float gt = 0.0f;
                    if (mm[u] != 0)
                        gt = 0.5f + 0.5f * (gc[u] * gr) - 0.5f * s[u];
                    local += sp - z * gt;
                }
            }
        }

        #pragma unroll
        for (int off = 16; off > 0; off >>= 1)
            local += __shfl_down_sync(0xffffffffu, local, off);
        if ((tid & 31) == 0) s_warp[tid >> 5] = local;
        __syncthreads();
        if (tid == 0)
            g_aux_partial[blk] = s_warp[0] + s_warp[1] + s_warp[2] + s_warp[3];
    } else {
        // ======== motion MLP loss (512 lanes over 4 blocks) ========
        const int mt = (blk - AUX_BLOCKS) * NTHR + tid;   // 0..511
        float part = 0.0f;
        {
            const int b  = mt >> 2;
            const int og = mt & 3;

            const float x0 = (float)goal_pixel[2 * b + 0];
            const float x1 = (float)goal_pixel[2 * b + 1];

            float h[HID];
            #pragma unroll
            for (int j = 0; j < HID; j++) {
                float v = fmaf(x0, w1[j], fmaf(x1, w1[HID + j], b1[j]));
                h[j] = fmaxf(v, 0.0f);
            }
            float acc[9];
            #pragma unroll
            for (int u = 0; u < 9; u++) acc[u] = b2[og * 9 + u];
            for (int j = 0; j < HID; j++) {
                const float hv = h[j];
                const float* wr = w2 + j * OUTD + og * 9;
                #pragma unroll
                for (int u = 0; u < 9; u++)
                    acc[u] = fmaf(hv, wr[u], acc[u]);
            }
            #pragma unroll
            for (int u = 0; u < 9; u++) {
                const int o = og * 9 + u;
                const int t = o / 3, uu = o % 3;
                const float tgt = (uu < 2) ? tpos[(b * TT + t) * 2 + uu]
                                           : tyaw[b * TT + t];
                const float d = acc[u] - tgt;
                part = fmaf(d, d, part);
            }
        }
        #pragma unroll
        for (int off = 16; off > 0; off >>= 1)
            part += __shfl_down_sync(0xffffffffu, part, off);
        if ((tid & 31) == 0) s_warp[tid >> 5] = part;
        __syncthreads();
        if (tid == 0)
            g_mot_partial[blk - AUX_BLOCKS] =
                s_warp[0] + s_warp[1] + s_warp[2] + s_warp[3];
    }

    // ======== last-block-done final combine ========
    __syncthreads();
    __threadfence();
    if (tid == 0) {
        int old = atomicAdd(&g_count, 1);
        s_last = (old == NBLK - 1);
    }
    __syncthreads();

    if (s_last) {
        __threadfence();
        float v = g_aux_partial[tid];        // 128 partials, 1 per thread
        #pragma unroll
        for (int off = 16; off > 0; off >>= 1)
            v += __shfl_down_sync(0xffffffffu, v, off);
        if ((tid & 31) == 0) s_warp[tid >> 5] = v;
        __syncthreads();
        if (tid == 0) {
            const float aux = s_warp[0] + s_warp[1] + s_warp[2] + s_warp[3];
            const float mot = (g_mot_partial[0] + g_mot_partial[1]
                             + g_mot_partial[2] + g_mot_partial[3])
                              * (1.0f / (float)(BB * OUTD));
            out[0] = mot + aux;
            out[1] = aux;
            out[2] = mot;
            g_count = 0;   // reset for next graph replay
        }
    }
}

extern "C" void kernel_launch(void* const* d_in, const int* in_sizes, int n_in,
                              void* d_out, int out_size)
{
    const int*   goal_pixel = (const int*)  d_in[0];
    const int*   obj_list   = (const int*)  d_in[1];
    const int*   obj_num    = (const int*)  d_in[2];
    const int*   road_mask  = (const int*)  d_in[3];
    const float* logits     = (const float*)d_in[4];
    const float* tpos       = (const float*)d_in[5];
    const float* tyaw       = (const float*)d_in[6];
    const float* w1         = (const float*)d_in[7];
    const float* b1         = (const float*)d_in[8];
    const float* w2         = (const float*)d_in[9];
    const float* b2         = (const float*)d_in[10];
    float* out = (float*)d_out;

    fused_kernel<<<NBLK, NTHR>>>(goal_pixel, obj_list, obj_num, road_mask,
                                 logits, tpos, tyaw, w1, b1, w2, b2, out);
}

// round 17
// speedup vs baseline: 1.0251x; 1.0226x over previous
#include <cuda_runtime.h>

// Problem constants
#define HH   112
#define WW   112
#define CROP 28
#define CW   56
#define NPIX (CW * CW)
#define BB   128
#define MM   64
#define TT   12
#define HID  64
#define OUTD 36

#define NTHR 128
#define AUX_BLOCKS BB            // 1 block per batch
#define MOT_BLOCKS 4
#define NBLK (AUX_BLOCKS + MOT_BLOCKS)   // 132 <= 148 : one wave

__device__ float g_aux_partial[AUX_BLOCKS];
__device__ float g_mot_partial[MOT_BLOCKS];
__device__ int   g_count = 0;

#define FMA2(acc, x, y) \
    asm("fma.rn.f32x2 %0, %1, %2, %0;" : "+l"(acc) : "l"(x), "l"(y))

__global__ __launch_bounds__(NTHR) void fused_kernel(
    const int*   __restrict__ goal_pixel,   // [B,2] (col,row)
    const int*   __restrict__ obj_list,     // [B,M,2] (col,row)
    const int*   __restrict__ obj_num,      // [B]
    const int*   __restrict__ road_mask,    // [B,112,112]
    const float* __restrict__ logits,       // [B,56,56]
    const float* __restrict__ tpos,         // [B,T,2]
    const float* __restrict__ tyaw,         // [B,T]
    const float* __restrict__ w1, const float* __restrict__ b1,
    const float* __restrict__ w2, const float* __restrict__ b2,
    float*       __restrict__ out)
{
    const int blk = blockIdx.x;
    const int tid = threadIdx.x;

    // smem: rowfd first for 16B alignment
    __shared__ __align__(16) unsigned long long rowfd[MM * CW]; // 28KB [m][r] dup'd
    __shared__ __align__(16) float colf[MM * 64];               // 16KB [m][c]
    __shared__ float tabc[384];      // exp(-(i-112)^2/8); zero for far indices
    __shared__ int   s_ox[MM], s_oy[MM];
    __shared__ float s_warp[4];
    __shared__ bool  s_last;

    if (blk < AUX_BLOCKS) {
        // ======== aux: one full 56x56 crop of one batch ========
        const int b  = blk;
        const int rt = tid >> 4;          // row tile 0..7 (7 valid)
        const int ct = tid & 15;          // col tile 0..15 (14 valid)
        const int rteff = (rt < 7) ? rt : 6;

        for (int i = tid; i < 384; i += NTHR) {
            float d = (float)(i - 112);
            tabc[i] = __expf(-d * d * 0.125f);
        }
        if (tid < MM) {
            int nobj = obj_num[b];
            nobj = nobj < 0 ? 0 : (nobj > MM ? MM : nobj);
            int2 o = ((const int2*)obj_list)[b * MM + tid];
            if (tid >= nobj) { o.x = -160; o.y = -160; }  // -> zero zone
            s_ox[tid] = o.x;   // col
            s_oy[tid] = o.y;   // row
        }
        const int yg = goal_pixel[2 * b + 0];
        const int xg = goal_pixel[2 * b + 1];
        __syncthreads();

        // colf[m][c] = tab(c+28 - ox[m]), c in [0,64)
        for (int i = tid; i < MM * 64; i += NTHR) {
            const int m = i >> 6, c = i & 63;
            colf[i] = tabc[c + CROP + 112 - s_ox[m]];
        }
        // rowfd[m][r] = dup(tab(r+28 - oy[m])), r in [0,56)
        for (int i = tid; i < MM * CW; i += NTHR) {
            const int m = i / CW, r = i - m * CW;
            const float v = tabc[r + CROP + 112 - s_oy[m]];
            unsigned long long d;
            asm("mov.b64 %0, {%1, %1};" : "=l"(d) : "f"(v));
            rowfd[i] = d;
        }
        __syncthreads();

        // ======== object loop: 16 f32x2 accumulators, rt-bound FFMA2 ========
        unsigned long long a[16];
        #pragma unroll
        for (int i = 0; i < 16; i++) a[i] = 0ull;

        const ulonglong2* pc = ((const ulonglong2*)colf) + ct;       // + m*16
        const ulonglong2* pr = ((const ulonglong2*)rowfd) + rteff * 4; // + m*28

        #pragma unroll
        for (int m = 0; m < MM; m++) {
            const ulonglong2 cf  = pc[m * 16];      // (c0,c1),(c2,c3)
            const ulonglong2 r01 = pr[m * 28 + 0];  // dup r0, dup r1
            const ulonglong2 r23 = pr[m * 28 + 1];
            const ulonglong2 r45 = pr[m * 28 + 2];
            const ulonglong2 r67 = pr[m * 28 + 3];
            FMA2(a[0],  cf.x, r01.x); FMA2(a[1],  cf.y, r01.x);
            FMA2(a[2],  cf.x, r01.y); FMA2(a[3],  cf.y, r01.y);
            FMA2(a[4],  cf.x, r23.x); FMA2(a[5],  cf.y, r23.x);
            FMA2(a[6],  cf.x, r23.y); FMA2(a[7],  cf.y, r23.y);
            FMA2(a[8],  cf.x, r45.x); FMA2(a[9],  cf.y, r45.x);
            FMA2(a[10], cf.x, r45.y); FMA2(a[11], cf.y, r45.y);
            FMA2(a[12], cf.x, r67.x); FMA2(a[13], cf.y, r67.x);
            FMA2(a[14], cf.x, r67.y); FMA2(a[15], cf.y, r67.y);
        }

        // ======== epilogue: softplus + BCE over this thread's 8x4 tile ========
        float local = 0.0f;
        if (rt < 7 && ct < 14) {
            const int r0 = rt * 8, c0 = ct * 4;
            const float4* lg = (const float4*)(logits + b * NPIX + r0 * CW + c0);
            const int4*   rm = (const int4*)(road_mask
                               + (b * HH + r0 + CROP) * WW + c0 + CROP);
            float gc[4];
            #pragma unroll
            for (int u = 0; u < 4; u++)
                gc[u] = tabc[c0 + u + CROP + 112 - yg];

            #pragma unroll
            for (int k = 0; k < 8; k++) {
                const float4 z4 = lg[k * (CW / 4)];
                const int4   m4 = rm[k * (WW / 4)];
                const float  gr = tabc[r0 + k + CROP + 112 - xg];
                float s[4];
                asm("mov.b64 {%0, %1}, %2;" : "=f"(s[0]), "=f"(s[1]) : "l"(a[2*k]));
                asm("mov.b64 {%0, %1}, %2;" : "=f"(s[2]), "=f"(s[3]) : "l"(a[2*k+1]));
                const float zz[4] = {z4.x, z4.y, z4.z, z4.w};
                const int   mm[4] = {m4.x, m4.y, m4.z, m4.w};
                #pragma unroll
                for (int u = 0; u < 4; u++) {
                    const float z  = zz[u];
                    const float sp = fmaxf(z, 0.0f)
                                   + __logf(1.0f + __expf(-fabsf(z)));
                    float gt = 0.0f;
                    if (mm[u] != 0)
                        gt = 0.5f + 0.5f * (gc[u] * gr) - 0.5f * s[u];
                    local += sp - z * gt;
                }
            }
        }

        #pragma unroll
        for (int off = 16; off > 0; off >>= 1)
            local += __shfl_down_sync(0xffffffffu, local, off);
        if ((tid & 31) == 0) s_warp[tid >> 5] = local;
        __syncthreads();
        if (tid == 0)
            g_aux_partial[blk] = s_warp[0] + s_warp[1] + s_warp[2] + s_warp[3];
    } else {
        // ======== motion MLP loss (512 lanes over 4 blocks) ========
        const int mt = (blk - AUX_BLOCKS) * NTHR + tid;   // 0..511
        float part = 0.0f;
        {
            const int b  = mt >> 2;
            const int og = mt & 3;

            const float x0 = (float)goal_pixel[2 * b + 0];
            const float x1 = (float)goal_pixel[2 * b + 1];

            float h[HID];
            #pragma unroll
            for (int j = 0; j < HID; j++) {
                float v = fmaf(x0, w1[j], fmaf(x1, w1[HID + j], b1[j]));
                h[j] = fmaxf(v, 0.0f);
            }
            float acc[9];
            #pragma unroll
            for (int u = 0; u < 9; u++) acc[u] = b2[og * 9 + u];
            for (int j = 0; j < HID; j++) {
                const float hv = h[j];
                const float* wr = w2 + j * OUTD + og * 9;
                #pragma unroll
                for (int u = 0; u < 9; u++)
                    acc[u] = fmaf(hv, wr[u], acc[u]);
            }
            #pragma unroll
            for (int u = 0; u < 9; u++) {
                const int o = og * 9 + u;
                const int t = o / 3, uu = o % 3;
                const float tgt = (uu < 2) ? tpos[(b * TT + t) * 2 + uu]
                                           : tyaw[b * TT + t];
                const float d = acc[u] - tgt;
                part = fmaf(d, d, part);
            }
        }
        #pragma unroll
        for (int off = 16; off > 0; off >>= 1)
            part += __shfl_down_sync(0xffffffffu, part, off);
        if ((tid & 31) == 0) s_warp[tid >> 5] = part;
        __syncthreads();
        if (tid == 0)
            g_mot_partial[blk - AUX_BLOCKS] =
                s_warp[0] + s_warp[1] + s_warp[2] + s_warp[3];
    }

    // ======== last-block-done final combine ========
    __syncthreads();
    __threadfence();
    if (tid == 0) {
        int old = atomicAdd(&g_count, 1);
        s_last = (old == NBLK - 1);
    }
    __syncthreads();

    if (s_last) {
        __threadfence();
        float v = g_aux_partial[tid];        // 128 partials, 1 per thread
        #pragma unroll
        for (int off = 16; off > 0; off >>= 1)
            v += __shfl_down_sync(0xffffffffu, v, off);
        if ((tid & 31) == 0) s_warp[tid >> 5] = v;
        __syncthreads();
        if (tid == 0) {
            const float aux = s_warp[0] + s_warp[1] + s_warp[2] + s_warp[3];
            const float mot = (g_mot_partial[0] + g_mot_partial[1]
                             + g_mot_partial[2] + g_mot_partial[3])
                              * (1.0f / (float)(BB * OUTD));
            out[0] = mot + aux;
            out[1] = aux;
            out[2] = mot;
            g_count = 0;   // reset for next graph replay
        }
    }
}

extern "C" void kernel_launch(void* const* d_in, const int* in_sizes, int n_in,
                              void* d_out, int out_size)
{
    const int*   goal_pixel = (const int*)  d_in[0];
    const int*   obj_list   = (const int*)  d_in[1];
    const int*   obj_num    = (const int*)  d_in[2];
    const int*   road_mask  = (const int*)  d_in[3];
    const float* logits     = (const float*)d_in[4];
    const float* tpos       = (const float*)d_in[5];
    const float* tyaw       = (const float*)d_in[6];
    const float* w1         = (const float*)d_in[7];
    const float* b1         = (const float*)d_in[8];
    const float* w2         = (const float*)d_in[9];
    const float* b2         = (const float*)d_in[10];
    float* out = (float*)d_out;

    fused_kernel<<<NBLK, NTHR>>>(goal_pixel, obj_list, obj_num, road_mask,
                                 logits, tpos, tyaw, w1, b1, w2, b2, out);
}